// round 1
// baseline (speedup 1.0000x reference)
#include <cuda_runtime.h>
#include <math.h>

// ---------------- problem constants ----------------
#define CB 2
#define CN 256
#define CM 8
#define CD 256
#define CH 8
#define CDH 64
#define CINNER 512          // H*DH
#define ROWS (CB*CN*CM)     // 4096 rows of [.,D]
#define ATT_SCALE 0.125f    // DH^-0.5
#define LNEPS 1e-5f

// ---------------- scratch (device globals; no allocs allowed) ----------------
__device__ float g_xt  [ROWS*CD];            // [B,N,M,D]            1M
__device__ float g_q   [ROWS*CINNER];        // [B,N,M,INNER]        2M
__device__ float g_kv  [ROWS*2*CINNER];      // [B,N,M,2*INNER]      4M
__device__ float g_S   [(size_t)CB*CH*CM*CM*CN*CN]; // [b,h,m,z,i,j] 67.1M (256MB)
__device__ float g_outb[ROWS*CD];            // [B,N, M*H*DH=4096] -> 2M? (B*N*4096 = 2M)
__device__ float g_outb_pad[ROWS*CD];        // (combined with above: need 2M floats total)
__device__ float g_o   [ROWS*CD];            // [B,N,M,D] (o proj)   1M
__device__ float g_y   [ROWS*CD];            // post-LN1             1M
__device__ float g_hg  [ROWS*2048];          // FFN hidden (2*D*4)   8M
__device__ float g_ffh [ROWS*1024];          // a*gelu(gate)         4M
__device__ float g_ff  [ROWS*CD];            // FFN out              1M

// ---------------- transpose x[B,D,M,N] -> xt[B,N,M,D] ----------------
__global__ void k_transpose(const float* __restrict__ x, float* __restrict__ xt) {
    __shared__ float tile[32][33];
    int bm = blockIdx.z;               // b*M+m
    int b = bm >> 3, m = bm & 7;
    int n0 = blockIdx.x * 32, d0 = blockIdx.y * 32;
    for (int r = threadIdx.y; r < 32; r += 8) {
        // read x[b, d0+r, m, n0+tx]  (n contiguous)
        tile[r][threadIdx.x] =
            x[(((size_t)b*CD + d0 + r)*CM + m)*CN + n0 + threadIdx.x];
    }
    __syncthreads();
    for (int r = threadIdx.y; r < 32; r += 8) {
        // write xt[b, n0+r, m, d0+tx]  (d contiguous)
        xt[(((size_t)b*CN + n0 + r)*CM + m)*CD + d0 + threadIdx.x] = tile[threadIdx.x][r];
    }
}

// ---------------- generic tiled SGEMM: C[Mr,Nc] = A[Mr,K] @ B[K,Nc] (+bias) ----------------
// BM=BN=64, BK=16, 256 threads, 4x4 per thread. Mr%64==0, Nc%64==0, K%16==0.
__global__ void k_gemm_nn(const float* __restrict__ A, const float* __restrict__ B,
                          const float* __restrict__ bias, float* __restrict__ C,
                          int Mr, int Nc, int K) {
    __shared__ float As[16][65];   // [k][row]
    __shared__ float Bs[16][65];   // [k][col]
    int tid = threadIdx.x;
    int tx = tid & 15, ty = tid >> 4;
    int row0 = blockIdx.y * 64, col0 = blockIdx.x * 64;
    float acc[4][4] = {};
    for (int k0 = 0; k0 < K; k0 += 16) {
        #pragma unroll
        for (int i = 0; i < 4; i++) {
            int r = ty + i*16;                 // row in tile
            As[tx][r] = A[(size_t)(row0 + r)*K + k0 + tx];
        }
        #pragma unroll
        for (int i = 0; i < 4; i++) {
            int e = tid + i*256; int r = e >> 6, c = e & 63;
            Bs[r][c] = B[(size_t)(k0 + r)*Nc + col0 + c];
        }
        __syncthreads();
        #pragma unroll
        for (int k = 0; k < 16; k++) {
            float a[4], bb[4];
            #pragma unroll
            for (int i = 0; i < 4; i++) a[i]  = As[k][ty*4 + i];
            #pragma unroll
            for (int j = 0; j < 4; j++) bb[j] = Bs[k][tx*4 + j];
            #pragma unroll
            for (int i = 0; i < 4; i++)
                #pragma unroll
                for (int j = 0; j < 4; j++) acc[i][j] += a[i]*bb[j];
        }
        __syncthreads();
    }
    #pragma unroll
    for (int i = 0; i < 4; i++)
        #pragma unroll
        for (int j = 0; j < 4; j++) {
            int r = row0 + ty*4 + i, c = col0 + tx*4 + j;
            float v = acc[i][j];
            if (bias) v += bias[c];
            C[(size_t)r*Nc + c] = v;
        }
}

// ---------------- sim: S[b,h,m,z,i,j] = scale * sum_d q[b,i,m,h,d]*k[b,j,z,h,d] ----------------
// grid: (j_tiles=4, i_tiles=4, zz=b*512+h*64+m*8+z -> 1024)
__global__ void k_sim(const float* __restrict__ q, const float* __restrict__ kv,
                      float* __restrict__ S) {
    __shared__ float Qs[64][65];   // [d][i]
    __shared__ float Ks[64][65];   // [d][j]
    int zz = blockIdx.z;
    int z = zz & 7, m = (zz >> 3) & 7, h = (zz >> 6) & 7, b = zz >> 9;
    int i0 = blockIdx.y * 64, j0 = blockIdx.x * 64;
    const float* Qb = q  + ((size_t)b*CN*CM + m)*CINNER     + h*CDH;   // + i*CM*CINNER
    const float* Kb = kv + ((size_t)b*CN*CM + z)*(2*CINNER) + h*CDH;   // + j*CM*2*CINNER
    int tid = threadIdx.x, tx = tid & 15, ty = tid >> 4;
    #pragma unroll
    for (int t = 0; t < 16; t++) {
        int e = tid + t*256; int r = e >> 6, c = e & 63;  // r = local row, c = d
        Qs[c][r] = Qb[(size_t)(i0 + r)*CM*CINNER + c];
        Ks[c][r] = Kb[(size_t)(j0 + r)*CM*2*CINNER + c];
    }
    __syncthreads();
    float acc[4][4] = {};
    #pragma unroll 8
    for (int k = 0; k < 64; k++) {
        float a[4], bb[4];
        #pragma unroll
        for (int i = 0; i < 4; i++) a[i]  = Qs[k][ty*4 + i];
        #pragma unroll
        for (int j = 0; j < 4; j++) bb[j] = Ks[k][tx*4 + j];
        #pragma unroll
        for (int i = 0; i < 4; i++)
            #pragma unroll
            for (int j = 0; j < 4; j++) acc[i][j] += a[i]*bb[j];
    }
    float* Cb = S + (size_t)zz * 65536;
    #pragma unroll
    for (int i = 0; i < 4; i++)
        #pragma unroll
        for (int j = 0; j < 4; j++)
            Cb[(size_t)(i0 + ty*4 + i)*256 + j0 + tx*4 + j] = acc[i][j] * ATT_SCALE;
}

// ---------------- softmax over i (query axis!) for fixed (b,h,m,z,j) ----------------
// grid: 1024 blocks (one per [b,h,m,z] slab of [256 i][256 j]), 256 threads = j
__global__ void k_softmax(float* __restrict__ S) {
    float* base = S + (size_t)blockIdx.x * 65536 + threadIdx.x;
    float mx = -1e30f, s = 0.f;
    for (int i = 0; i < 256; i++) {
        float x = base[(size_t)i * 256];
        if (x > mx) { s = s * expf(mx - x) + 1.f; mx = x; }
        else        { s += expf(x - mx); }
    }
    float inv = 1.f / s;
    for (int i = 0; i < 256; i++) {
        size_t off = (size_t)i * 256;
        base[off] = expf(base[off] - mx) * inv;
    }
}

// ---------------- out[b,i,z,h,d] = sum_{j,m} A[b,h,m,z,i,j] * v[b,j,m,h,d] ----------------
// grid: (i_tiles=4, v=b*64+h*8+z -> 128), 256 threads, tile [64 i][64 d]
__global__ void k_av(const float* __restrict__ S, const float* __restrict__ kv,
                     float* __restrict__ outb) {
    __shared__ float As[64][65];   // [j][i]
    __shared__ float Vs[64][65];   // [j][d]
    int v = blockIdx.y;
    int z = v & 7, h = (v >> 3) & 7, b = v >> 6;
    int i0 = blockIdx.x * 64;
    int tid = threadIdx.x, tx = tid & 15, ty = tid >> 4;
    const float* Vb0 = kv + (size_t)b*CN*CM*(2*CINNER) + CINNER + h*CDH;
    float acc[4][4] = {};
    for (int m = 0; m < CM; m++) {
        const float* Ab = S + ((((size_t)((b*8 + h)*8 + m))*8 + z) * 65536);
        for (int j0 = 0; j0 < 256; j0 += 64) {
            #pragma unroll
            for (int t = 0; t < 16; t++) {
                int e = tid + t*256; int r = e >> 6, c = e & 63;
                As[c][r] = Ab[(size_t)(i0 + r)*256 + j0 + c];            // c=j local, r=i local
                Vs[r][c] = Vb0[((size_t)(j0 + r)*CM + m)*(2*CINNER) + c]; // r=j local, c=d
            }
            __syncthreads();
            #pragma unroll 8
            for (int k = 0; k < 64; k++) {
                float a[4], vv[4];
                #pragma unroll
                for (int i = 0; i < 4; i++) a[i]  = As[k][ty*4 + i];
                #pragma unroll
                for (int j = 0; j < 4; j++) vv[j] = Vs[k][tx*4 + j];
                #pragma unroll
                for (int i = 0; i < 4; i++)
                    #pragma unroll
                    for (int j = 0; j < 4; j++) acc[i][j] += a[i]*vv[j];
            }
            __syncthreads();
        }
    }
    // outb[b, i, z*512 + h*64 + d]   ('b n (z h d)')
    #pragma unroll
    for (int i = 0; i < 4; i++)
        #pragma unroll
        for (int j = 0; j < 4; j++) {
            int ii = i0 + ty*4 + i, d = tx*4 + j;
            outb[((size_t)b*CN + ii)*4096 + z*CINNER + h*CDH + d] = acc[i][j];
        }
}

// ---------------- residual add + LayerNorm over D=256 ----------------
__global__ void k_addln(const float* __restrict__ a, const float* __restrict__ bb,
                        const float* __restrict__ g, const float* __restrict__ beta,
                        float* __restrict__ out) {
    __shared__ float red[256];
    int r = blockIdx.x, d = threadIdx.x;
    float v = a[(size_t)r*256 + d] + bb[(size_t)r*256 + d];
    red[d] = v; __syncthreads();
    for (int s = 128; s > 0; s >>= 1) { if (d < s) red[d] += red[d + s]; __syncthreads(); }
    float mu = red[0] * (1.f/256.f);
    __syncthreads();
    float c = v - mu;
    red[d] = c * c; __syncthreads();
    for (int s = 128; s > 0; s >>= 1) { if (d < s) red[d] += red[d + s]; __syncthreads(); }
    float var = red[0] * (1.f/256.f);
    out[(size_t)r*256 + d] = c * rsqrtf(var + LNEPS) * g[d] + beta[d];
}

// ---------------- GEGLU: ffh[r,c] = hg[r,c] * gelu_exact(hg[r,1024+c]) ----------------
__global__ void k_geglu(const float* __restrict__ hg, float* __restrict__ ffh) {
    int idx = blockIdx.x * blockDim.x + threadIdx.x;   // 4096*1024
    int r = idx >> 10, c = idx & 1023;
    float a  = hg[(size_t)r*2048 + c];
    float gt = hg[(size_t)r*2048 + 1024 + c];
    float ge = gt * 0.5f * (1.f + erff(gt * 0.70710678118654752f));
    ffh[idx] = a * ge;
}

// ---------------- launch ----------------
extern "C" void kernel_launch(void* const* d_in, const int* in_sizes, int n_in,
                              void* d_out, int out_size) {
    const float* x     = (const float*)d_in[0];
    const float* Wq    = (const float*)d_in[1];
    const float* Wkv   = (const float*)d_in[2];
    const float* Wout  = (const float*)d_in[3];
    const float* bout  = (const float*)d_in[4];
    const float* g1    = (const float*)d_in[5];
    const float* beta1 = (const float*)d_in[6];
    const float* Wff1  = (const float*)d_in[7];
    const float* bff1  = (const float*)d_in[8];
    const float* Wff2  = (const float*)d_in[9];
    const float* bff2  = (const float*)d_in[10];
    const float* g2    = (const float*)d_in[11];
    const float* beta2 = (const float*)d_in[12];
    float* out = (float*)d_out;

    float *xt, *q, *kv, *S, *outb, *o, *y, *hg, *ffh, *ff;
    cudaGetSymbolAddress((void**)&xt,   g_xt);
    cudaGetSymbolAddress((void**)&q,    g_q);
    cudaGetSymbolAddress((void**)&kv,   g_kv);
    cudaGetSymbolAddress((void**)&S,    g_S);
    cudaGetSymbolAddress((void**)&outb, g_outb);   // uses g_outb + g_outb_pad? no: outb is 2M floats
    cudaGetSymbolAddress((void**)&o,    g_o);
    cudaGetSymbolAddress((void**)&y,    g_y);
    cudaGetSymbolAddress((void**)&hg,   g_hg);
    cudaGetSymbolAddress((void**)&ffh,  g_ffh);
    cudaGetSymbolAddress((void**)&ff,   g_ff);
    // NOTE: outb needs B*N*4096 = 2,097,152 floats; g_outb alone is ROWS*CD = 1,048,576.
    // g_outb and g_outb_pad are declared adjacent but adjacency is NOT guaranteed,
    // so repurpose g_hg (8M floats, not yet live) as outb scratch instead:
    outb = hg;   // outb uses first 2M floats of g_hg; hg itself is consumed later, after outb is dead? 
    // CAREFUL: outb is read by the Wout GEMM (step 7) and dead afterwards; hg is written
    // in step 9. No overlap in lifetime -> safe to alias. o (1M) is separate.

    // 1. transpose
    k_transpose<<<dim3(8, 8, 16), dim3(32, 8)>>>(x, xt);
    // 2-3. Q and KV projections
    k_gemm_nn<<<dim3(8, 64),  256>>>(xt, Wq,  nullptr, q,  4096, 512,  256);
    k_gemm_nn<<<dim3(16, 64), 256>>>(xt, Wkv, nullptr, kv, 4096, 1024, 256);
    // 4. sim (batched NT gemm into [b,h,m,z,i,j])
    k_sim<<<dim3(4, 4, 1024), 256>>>(q, kv, S);
    // 5. softmax over i
    k_softmax<<<1024, 256>>>(S);
    // 6. attn @ V  -> outb [B,N, (z h d)=4096]
    k_av<<<dim3(4, 128), 256>>>(S, kv, outb);
    // 7. Wout projection: [512,4096]@[4096,2048]+bout -> o (viewed [4096,256])
    k_gemm_nn<<<dim3(32, 8), 256>>>(outb, Wout, bout, o, 512, 2048, 4096);
    // 8. residual + LN1 -> y
    k_addln<<<4096, 256>>>(xt, o, g1, beta1, y);
    // 9. FFN in: [4096,256]@[256,2048]+bff1 -> hg   (outb region of g_hg now dead)
    k_gemm_nn<<<dim3(32, 64), 256>>>(y, Wff1, bff1, hg, 4096, 2048, 256);
    // 10. GEGLU -> ffh [4096,1024]
    k_geglu<<<16384, 256>>>(hg, ffh);
    // 11. FFN out: [4096,1024]@[1024,256]+bff2 -> ff
    k_gemm_nn<<<dim3(4, 64), 256>>>(ffh, Wff2, bff2, ff, 4096, 256, 1024);
    // 12. residual + LN2 -> output (reference returns a VIEW: output memory = [B,N,M,D] linearized)
    k_addln<<<4096, 256>>>(y, ff, g2, beta2, out);
}

// round 2
// speedup vs baseline: 1.4738x; 1.4738x over previous
#include <cuda_runtime.h>
#include <math.h>

// ---------------- problem constants ----------------
#define CB 2
#define CN 256
#define CM 8
#define CD 256
#define CH 8
#define CDH 64
#define CINNER 512          // H*DH
#define ROWS (CB*CN*CM)     // 4096 rows of [.,D]
#define ATT_SCALE 0.125f    // DH^-0.5
#define LNEPS 1e-5f
#define L2E 1.4426950408889634f

// ---------------- scratch (device globals; no allocs allowed) ----------------
__device__ float g_xt  [ROWS*CD];                    // [B,N,M,D]
__device__ float g_q   [ROWS*CINNER];                // [B,N,M,INNER]
__device__ float g_kv  [ROWS*2*CINNER];              // [B,N,M,2*INNER]
__device__ float g_S   [(size_t)CB*CH*CM*CM*CN*CN];  // [b,h,m,z,i,j]
__device__ float g_mx  [1024*256];                   // softmax max  per (slab, j)
__device__ float g_inv [1024*256];                   // softmax 1/sum per (slab, j)
__device__ float g_o   [ROWS*CD];
__device__ float g_y   [ROWS*CD];
__device__ float g_hg  [ROWS*2048];                  // also aliased as outb (first 2M floats)
__device__ float g_ffh [ROWS*1024];
__device__ float g_ff  [ROWS*CD];

// ---------------- transpose x[B,D,M,N] -> xt[B,N,M,D] ----------------
__global__ void k_transpose(const float* __restrict__ x, float* __restrict__ xt) {
    __shared__ float tile[32][33];
    int bm = blockIdx.z;
    int b = bm >> 3, m = bm & 7;
    int n0 = blockIdx.x * 32, d0 = blockIdx.y * 32;
    for (int r = threadIdx.y; r < 32; r += 8)
        tile[r][threadIdx.x] = x[(((size_t)b*CD + d0 + r)*CM + m)*CN + n0 + threadIdx.x];
    __syncthreads();
    for (int r = threadIdx.y; r < 32; r += 8)
        xt[(((size_t)b*CN + n0 + r)*CM + m)*CD + d0 + threadIdx.x] = tile[threadIdx.x][r];
}

// ================= GEMM 128x128, BK=16, 256 threads, 8x8/thread =================
// C[Mr,Nc] = A[Mr,K] @ B[K,Nc] (+bias). Mr%128==0, Nc%128==0, K%16==0.
__global__ void __launch_bounds__(256, 2)
k_gemm128(const float* __restrict__ A, const float* __restrict__ B,
          const float* __restrict__ bias, float* __restrict__ C,
          int Mr, int Nc, int K) {
    __shared__ float As[16][132];   // [k][row]
    __shared__ float Bs[16][132];   // [k][col]
    int t = threadIdx.x;
    int tx = t & 15, ty = t >> 4;            // tx: 16 col-groups of 8, ty: 16 row-groups of 8
    int row0 = blockIdx.y * 128, col0 = blockIdx.x * 128;
    float acc[8][8] = {};
    int arow = t >> 2, akt = (t & 3) * 4;    // A-load: 64 rows/pass, 2 passes
    int bkr = t >> 5, bc4 = (t & 31) * 4;    // B-load: 8 k-rows/pass, 2 passes
    for (int k0 = 0; k0 < K; k0 += 16) {
        #pragma unroll
        for (int p = 0; p < 2; p++) {
            int r = arow + p*64;
            float4 v = *(const float4*)&A[(size_t)(row0 + r)*K + k0 + akt];
            As[akt+0][r] = v.x; As[akt+1][r] = v.y; As[akt+2][r] = v.z; As[akt+3][r] = v.w;
        }
        #pragma unroll
        for (int p = 0; p < 2; p++) {
            int kr = bkr + p*8;
            *(float4*)&Bs[kr][bc4] = *(const float4*)&B[(size_t)(k0 + kr)*Nc + col0 + bc4];
        }
        __syncthreads();
        #pragma unroll
        for (int k = 0; k < 16; k++) {
            float a[8], bb[8];
            *(float4*)&a[0]  = *(const float4*)&As[k][ty*8];
            *(float4*)&a[4]  = *(const float4*)&As[k][ty*8+4];
            *(float4*)&bb[0] = *(const float4*)&Bs[k][tx*8];
            *(float4*)&bb[4] = *(const float4*)&Bs[k][tx*8+4];
            #pragma unroll
            for (int i = 0; i < 8; i++)
                #pragma unroll
                for (int j = 0; j < 8; j++) acc[i][j] += a[i]*bb[j];
        }
        __syncthreads();
    }
    #pragma unroll
    for (int i = 0; i < 8; i++) {
        int r = row0 + ty*8 + i;
        #pragma unroll
        for (int j4 = 0; j4 < 2; j4++) {
            int c = col0 + tx*8 + j4*4;
            float4 v = make_float4(acc[i][j4*4], acc[i][j4*4+1], acc[i][j4*4+2], acc[i][j4*4+3]);
            if (bias) { v.x += bias[c]; v.y += bias[c+1]; v.z += bias[c+2]; v.w += bias[c+3]; }
            *(float4*)&C[(size_t)r*Nc + c] = v;
        }
    }
}

// ================= GEMM 64x64, BK=32, 128 threads, 8x4/thread =================
// For skinny outputs / long K (Wout, FFN2). Mr%64==0, Nc%64==0, K%32==0.
__global__ void __launch_bounds__(128)
k_gemm64(const float* __restrict__ A, const float* __restrict__ B,
         const float* __restrict__ bias, float* __restrict__ C,
         int Mr, int Nc, int K) {
    __shared__ float As[32][68];   // [k][row]
    __shared__ float Bs[32][68];   // [k][col]
    int t = threadIdx.x;
    int tx = t & 15, ty = t >> 4;  // tx: 16 col-groups of 4, ty: 8 row-groups of 8
    int row0 = blockIdx.y * 64, col0 = blockIdx.x * 64;
    float acc[8][4] = {};
    for (int k0 = 0; k0 < K; k0 += 32) {
        #pragma unroll
        for (int p = 0; p < 4; p++) {
            int e = t + p*128;
            int r = e >> 3, k4 = (e & 7) * 4;
            float4 v = *(const float4*)&A[(size_t)(row0 + r)*K + k0 + k4];
            As[k4+0][r] = v.x; As[k4+1][r] = v.y; As[k4+2][r] = v.z; As[k4+3][r] = v.w;
        }
        #pragma unroll
        for (int p = 0; p < 4; p++) {
            int e = t + p*128;
            int kr = e >> 4, c4 = (e & 15) * 4;
            *(float4*)&Bs[kr][c4] = *(const float4*)&B[(size_t)(k0 + kr)*Nc + col0 + c4];
        }
        __syncthreads();
        #pragma unroll
        for (int k = 0; k < 32; k++) {
            float a[8], bb[4];
            *(float4*)&a[0] = *(const float4*)&As[k][ty*8];
            *(float4*)&a[4] = *(const float4*)&As[k][ty*8+4];
            *(float4*)&bb[0] = *(const float4*)&Bs[k][tx*4];
            #pragma unroll
            for (int i = 0; i < 8; i++)
                #pragma unroll
                for (int j = 0; j < 4; j++) acc[i][j] += a[i]*bb[j];
        }
        __syncthreads();
    }
    #pragma unroll
    for (int i = 0; i < 8; i++) {
        int r = row0 + ty*8 + i, c = col0 + tx*4;
        float4 v = make_float4(acc[i][0], acc[i][1], acc[i][2], acc[i][3]);
        if (bias) { v.x += bias[c]; v.y += bias[c+1]; v.z += bias[c+2]; v.w += bias[c+3]; }
        *(float4*)&C[(size_t)r*Nc + c] = v;
    }
}

// ================= sim: S[slab][i][j] = scale * q[b,i,m,h,:] . k[b,j,z,h,:] =================
// slab = ((b*8+h)*8+m)*8+z. Tile 128x128 over (i,j), K=64 in two 32-chunks.
__global__ void __launch_bounds__(256, 2)
k_sim(const float* __restrict__ q, const float* __restrict__ kv, float* __restrict__ S) {
    __shared__ float Qs[32][132];  // [d][i]
    __shared__ float Ks[32][132];  // [d][j]
    int zz = blockIdx.z;
    int z = zz & 7, m = (zz >> 3) & 7, h = (zz >> 6) & 7, b = zz >> 9;
    int i0 = blockIdx.y * 128, j0 = blockIdx.x * 128;
    const float* Qb = q  + ((size_t)b*CN*CM + m)*CINNER     + h*CDH;   // + i*4096
    const float* Kb = kv + ((size_t)b*CN*CM + z)*(2*CINNER) + h*CDH;   // + j*8192
    int t = threadIdx.x;
    int tx = t & 15, ty = t >> 4;
    float acc[8][8] = {};
    for (int d0 = 0; d0 < 64; d0 += 32) {
        #pragma unroll
        for (int p = 0; p < 4; p++) {
            int e = t + p*256;
            int r = e >> 3, k4 = (e & 7) * 4;
            float4 vq = *(const float4*)&Qb[(size_t)(i0 + r)*4096 + d0 + k4];
            Qs[k4+0][r] = vq.x; Qs[k4+1][r] = vq.y; Qs[k4+2][r] = vq.z; Qs[k4+3][r] = vq.w;
            float4 vk = *(const float4*)&Kb[(size_t)(j0 + r)*8192 + d0 + k4];
            Ks[k4+0][r] = vk.x; Ks[k4+1][r] = vk.y; Ks[k4+2][r] = vk.z; Ks[k4+3][r] = vk.w;
        }
        __syncthreads();
        #pragma unroll
        for (int k = 0; k < 32; k++) {
            float a[8], bb[8];
            *(float4*)&a[0]  = *(const float4*)&Qs[k][ty*8];
            *(float4*)&a[4]  = *(const float4*)&Qs[k][ty*8+4];
            *(float4*)&bb[0] = *(const float4*)&Ks[k][tx*8];
            *(float4*)&bb[4] = *(const float4*)&Ks[k][tx*8+4];
            #pragma unroll
            for (int i = 0; i < 8; i++)
                #pragma unroll
                for (int j = 0; j < 8; j++) acc[i][j] += a[i]*bb[j];
        }
        __syncthreads();
    }
    float* Cb = S + (size_t)zz * 65536;
    #pragma unroll
    for (int i = 0; i < 8; i++) {
        size_t roff = (size_t)(i0 + ty*8 + i)*256 + j0 + tx*8;
        #pragma unroll
        for (int j4 = 0; j4 < 2; j4++) {
            float4 v = make_float4(acc[i][j4*4]*ATT_SCALE, acc[i][j4*4+1]*ATT_SCALE,
                                   acc[i][j4*4+2]*ATT_SCALE, acc[i][j4*4+3]*ATT_SCALE);
            *(float4*)&Cb[roff + j4*4] = v;
        }
    }
}

// ================= softmax stats over i: per (slab, j) max and 1/sum =================
__global__ void k_stats(const float* __restrict__ S, float* __restrict__ mxo,
                        float* __restrict__ invo) {
    int slab = blockIdx.x, j = threadIdx.x;
    const float* base = S + (size_t)slab * 65536 + j;
    float mx = -1e30f, s = 0.f;
    for (int i = 0; i < 256; i++) {
        float x = base[(size_t)i * 256];
        if (x > mx) { s = s * exp2f((mx - x) * L2E) + 1.f; mx = x; }
        else        { s += exp2f((x - mx) * L2E); }
    }
    mxo[slab*256 + j] = mx;
    invo[slab*256 + j] = 1.f / s;
}

// ================= AV with fused softmax normalization =================
// outb[b, i, z*512 + h*64 + d] = sum_{m,j} softmax(S)[slab(b,h,m,z)][i][j] * v[b,j,m,h,d]
// grid (4 i-tiles, 128 = b*64+h*8+z), 128 threads, tile 64i x 64d, BK=32 (j), m outer.
__global__ void __launch_bounds__(128)
k_av(const float* __restrict__ S, const float* __restrict__ kv,
     const float* __restrict__ mxs, const float* __restrict__ invs,
     float* __restrict__ outb) {
    __shared__ float As[32][68];   // [j][i] (normalized probs)
    __shared__ float Vs[32][68];   // [j][d]
    __shared__ float smx[256], sinv[256];
    int v = blockIdx.y;
    int z = v & 7, h = (v >> 3) & 7, b = v >> 6;
    int i0 = blockIdx.x * 64;
    int t = threadIdx.x;
    int tx = t & 15, ty = t >> 4;
    int statbase = (((b*8 + h)*8)*8 + z);  // slab index for m=0; +64*m per m... recompute inside
    (void)statbase;
    const float* Vb0 = kv + (size_t)b*CN*CM*(2*CINNER) + CINNER + h*CDH;
    float acc[8][4] = {};
    for (int m = 0; m < CM; m++) {
        int slab = (((b*8 + h)*8 + m)*8 + z);
        // preload stats for this slab
        #pragma unroll
        for (int p = 0; p < 2; p++) {
            int jj = t + p*128;
            smx[jj]  = mxs[slab*256 + jj];
            sinv[jj] = invs[slab*256 + jj];
        }
        __syncthreads();
        const float* Ab = S + (size_t)slab * 65536;
        for (int j0 = 0; j0 < 256; j0 += 32) {
            #pragma unroll
            for (int p = 0; p < 4; p++) {
                int e = t + p*128;
                int r = e >> 3, j4 = (e & 7) * 4;        // r = i local (64), j4 = j local
                float4 x = *(const float4*)&Ab[(size_t)(i0 + r)*256 + j0 + j4];
                As[j4+0][r] = exp2f((x.x - smx[j0+j4+0]) * L2E) * sinv[j0+j4+0];
                As[j4+1][r] = exp2f((x.y - smx[j0+j4+1]) * L2E) * sinv[j0+j4+1];
                As[j4+2][r] = exp2f((x.z - smx[j0+j4+2]) * L2E) * sinv[j0+j4+2];
                As[j4+3][r] = exp2f((x.w - smx[j0+j4+3]) * L2E) * sinv[j0+j4+3];
                int jr = e >> 4, d4 = (e & 15) * 4;      // jr = j local (32), d4 = d
                *(float4*)&Vs[jr][d4] =
                    *(const float4*)&Vb0[((size_t)(j0 + jr)*CM + m)*(2*CINNER) + d4];
            }
            __syncthreads();
            #pragma unroll
            for (int k = 0; k < 32; k++) {
                float a[8], vv[4];
                *(float4*)&a[0] = *(const float4*)&As[k][ty*8];
                *(float4*)&a[4] = *(const float4*)&As[k][ty*8+4];
                *(float4*)&vv[0] = *(const float4*)&Vs[k][tx*4];
                #pragma unroll
                for (int i = 0; i < 8; i++)
                    #pragma unroll
                    for (int j = 0; j < 4; j++) acc[i][j] += a[i]*vv[j];
            }
            __syncthreads();
        }
    }
    #pragma unroll
    for (int i = 0; i < 8; i++) {
        int ii = i0 + ty*8 + i, d = tx*4;
        float4 o4 = make_float4(acc[i][0], acc[i][1], acc[i][2], acc[i][3]);
        *(float4*)&outb[((size_t)b*CN + ii)*4096 + z*CINNER + h*CDH + d] = o4;
    }
}

// ---------------- residual add + LayerNorm over D=256 ----------------
__global__ void k_addln(const float* __restrict__ a, const float* __restrict__ bb,
                        const float* __restrict__ g, const float* __restrict__ beta,
                        float* __restrict__ out) {
    __shared__ float red[256];
    int r = blockIdx.x, d = threadIdx.x;
    float v = a[(size_t)r*256 + d] + bb[(size_t)r*256 + d];
    red[d] = v; __syncthreads();
    for (int s = 128; s > 0; s >>= 1) { if (d < s) red[d] += red[d + s]; __syncthreads(); }
    float mu = red[0] * (1.f/256.f);
    __syncthreads();
    float c = v - mu;
    red[d] = c * c; __syncthreads();
    for (int s = 128; s > 0; s >>= 1) { if (d < s) red[d] += red[d + s]; __syncthreads(); }
    float var = red[0] * (1.f/256.f);
    out[(size_t)r*256 + d] = c * rsqrtf(var + LNEPS) * g[d] + beta[d];
}

// ---------------- GEGLU: ffh[r,c] = hg[r,c] * gelu_exact(hg[r,1024+c]) ----------------
__global__ void k_geglu(const float* __restrict__ hg, float* __restrict__ ffh) {
    int idx4 = blockIdx.x * blockDim.x + threadIdx.x;   // over 1M float4s
    int r = idx4 >> 8, c4 = (idx4 & 255) * 4;
    float4 a  = *(const float4*)&hg[(size_t)r*2048 + c4];
    float4 gt = *(const float4*)&hg[(size_t)r*2048 + 1024 + c4];
    float4 o;
    o.x = a.x * (gt.x * 0.5f * (1.f + erff(gt.x * 0.70710678f)));
    o.y = a.y * (gt.y * 0.5f * (1.f + erff(gt.y * 0.70710678f)));
    o.z = a.z * (gt.z * 0.5f * (1.f + erff(gt.z * 0.70710678f)));
    o.w = a.w * (gt.w * 0.5f * (1.f + erff(gt.w * 0.70710678f)));
    *(float4*)&ffh[(size_t)r*1024 + c4] = o;
}

// ---------------- launch ----------------
extern "C" void kernel_launch(void* const* d_in, const int* in_sizes, int n_in,
                              void* d_out, int out_size) {
    const float* x     = (const float*)d_in[0];
    const float* Wq    = (const float*)d_in[1];
    const float* Wkv   = (const float*)d_in[2];
    const float* Wout  = (const float*)d_in[3];
    const float* bout  = (const float*)d_in[4];
    const float* g1    = (const float*)d_in[5];
    const float* beta1 = (const float*)d_in[6];
    const float* Wff1  = (const float*)d_in[7];
    const float* bff1  = (const float*)d_in[8];
    const float* Wff2  = (const float*)d_in[9];
    const float* bff2  = (const float*)d_in[10];
    const float* g2    = (const float*)d_in[11];
    const float* beta2 = (const float*)d_in[12];
    float* out = (float*)d_out;

    float *xt, *q, *kv, *S, *mx, *inv, *o, *y, *hg, *ffh, *ff;
    cudaGetSymbolAddress((void**)&xt,  g_xt);
    cudaGetSymbolAddress((void**)&q,   g_q);
    cudaGetSymbolAddress((void**)&kv,  g_kv);
    cudaGetSymbolAddress((void**)&S,   g_S);
    cudaGetSymbolAddress((void**)&mx,  g_mx);
    cudaGetSymbolAddress((void**)&inv, g_inv);
    cudaGetSymbolAddress((void**)&o,   g_o);
    cudaGetSymbolAddress((void**)&y,   g_y);
    cudaGetSymbolAddress((void**)&hg,  g_hg);
    cudaGetSymbolAddress((void**)&ffh, g_ffh);
    cudaGetSymbolAddress((void**)&ff,  g_ff);
    // outb (2M floats) aliases start of g_hg: outb dies after Wout GEMM (step 7),
    // hg is first written in step 9 -> disjoint lifetimes, stream-serial order.
    float* outb = hg;

    // 1. transpose x -> xt
    k_transpose<<<dim3(8, 8, 16), dim3(32, 8)>>>(x, xt);
    // 2-3. Q and KV projections (4096 x {512,1024}, K=256)
    k_gemm128<<<dim3(4, 32),  256>>>(xt, Wq,  nullptr, q,  4096, 512,  256);
    k_gemm128<<<dim3(8, 32),  256>>>(xt, Wkv, nullptr, kv, 4096, 1024, 256);
    // 4. sim -> S [slab][i][j] (scaled)
    k_sim<<<dim3(2, 2, 1024), 256>>>(q, kv, S);
    // 5. softmax stats over i
    k_stats<<<1024, 256>>>(S, mx, inv);
    // 6. AV with fused normalization -> outb [B,N,(z h d)=4096]
    k_av<<<dim3(4, 128), 128>>>(S, kv, mx, inv, outb);
    // 7. Wout: [512,4096] @ [4096,2048] + bout -> o (viewed [4096,256])
    k_gemm64<<<dim3(32, 8), 128>>>(outb, Wout, bout, o, 512, 2048, 4096);
    // 8. residual + LN1 -> y
    k_addln<<<4096, 256>>>(xt, o, g1, beta1, y);
    // 9. FFN in: [4096,256] @ [256,2048] + bff1 -> hg
    k_gemm128<<<dim3(16, 32), 256>>>(y, Wff1, bff1, hg, 4096, 2048, 256);
    // 10. GEGLU -> ffh [4096,1024]
    k_geglu<<<4096, 256>>>(hg, ffh);
    // 11. FFN out: [4096,1024] @ [1024,256] + bff2 -> ff
    k_gemm64<<<dim3(4, 64), 128>>>(ffh, Wff2, bff2, ff, 4096, 256, 1024);
    // 12. residual + LN2 -> out (reference reshape is a view)
    k_addln<<<4096, 256>>>(y, ff, g2, beta2, out);
}